// round 17
// baseline (speedup 1.0000x reference)
#include <cuda_runtime.h>

#define NSC     4096
#define NT      14
#define THREADS 512
#define PAD(f)  ((f) + ((f) >> 3))
#define RSQ2    0.70710678118654752f
// shared (float2 units): Tb[0,256) | Y0[256,2560) | Y1[2560,4864) | R0[4864,5888) | R1[5888,6912)
#define SMEM_BYTES 55296

__constant__ float c_w[NT] = {0.f, 0.f, 0.f, 1.f/9, 2.f/9, 3.f/9, 4.f/9, 5.f/9,
                              6.f/9, 7.f/9, 8.f/9, 1.f, 1.f, 1.f};

__device__ __forceinline__ void hsync(int sel) {
    asm volatile("bar.sync %0, 256;" :: "r"(sel + 1) : "memory");
}

__device__ __forceinline__ float2 cadd(float2 a, float2 b) { return make_float2(a.x + b.x, a.y + b.y); }
__device__ __forceinline__ float2 csub(float2 a, float2 b) { return make_float2(a.x - b.x, a.y - b.y); }
__device__ __forceinline__ float2 cmul(float2 a, float2 b) {
    return make_float2(a.x * b.x - a.y * b.y, a.x * b.y + a.y * b.x);
}
__device__ __forceinline__ float2 shfl_xor_f2(float2 v, int mask) {
    float2 r;
    r.x = __shfl_xor_sync(0xFFFFFFFFu, v.x, mask);
    r.y = __shfl_xor_sync(0xFFFFFFFFu, v.y, mask);
    return r;
}

// Forward radix-8 DIF stage (L=8h). Twiddle index j*str <= 255.
__device__ __forceinline__ void fwd8(float2* __restrict__ A, const float2* __restrict__ Tb,
                                     int q, int h, int str) {
    int j    = q & (h - 1);
    int base = ((q - j) << 3) + j;
    float2 t0 = A[PAD(base)],         t1 = A[PAD(base + h)];
    float2 t2 = A[PAD(base + 2 * h)], t3 = A[PAD(base + 3 * h)];
    float2 t4 = A[PAD(base + 4 * h)], t5 = A[PAD(base + 5 * h)];
    float2 t6 = A[PAD(base + 6 * h)], t7 = A[PAD(base + 7 * h)];

    float2 a0 = cadd(t0, t4), a1 = cadd(t1, t5), a2 = cadd(t2, t6), a3 = cadd(t3, t7);
    float2 b0 = csub(t0, t4), b1 = csub(t1, t5), b2 = csub(t2, t6), b3 = csub(t3, t7);
    float2 c0 = cadd(a0, a2), c1 = csub(a0, a2), c2 = cadd(a1, a3), c3 = csub(a1, a3);
    float2 X0 = cadd(c0, c2), X4 = csub(c0, c2);
    float2 X2 = make_float2(c1.x + c3.y, c1.y - c3.x);
    float2 X6 = make_float2(c1.x - c3.y, c1.y + c3.x);
    float2 d0 = b0;
    float2 d1 = make_float2(RSQ2 * (b1.x + b1.y), RSQ2 * (b1.y - b1.x));
    float2 d2 = make_float2(b2.y, -b2.x);
    float2 d3 = make_float2(RSQ2 * (b3.y - b3.x), RSQ2 * (-(b3.x + b3.y)));
    float2 e0 = cadd(d0, d2), ee1 = csub(d0, d2), e2 = cadd(d1, d3), e3 = csub(d1, d3);
    float2 X1 = cadd(e0, e2), X5 = csub(e0, e2);
    float2 X3 = make_float2(ee1.x + e3.y, ee1.y - e3.x);
    float2 X7 = make_float2(ee1.x - e3.y, ee1.y + e3.x);

    float2 w1 = Tb[j * str]; w1.y = -w1.y;
    float2 w2 = cmul(w1, w1);
    float2 w3 = cmul(w2, w1);
    float2 w4 = cmul(w2, w2);
    float2 w5 = cmul(w4, w1);
    float2 w6 = cmul(w4, w2);
    float2 w7 = cmul(w4, w3);
    A[PAD(base)]         = X0;
    A[PAD(base + h)]     = cmul(X1, w1);
    A[PAD(base + 2 * h)] = cmul(X2, w2);
    A[PAD(base + 3 * h)] = cmul(X3, w3);
    A[PAD(base + 4 * h)] = cmul(X4, w4);
    A[PAD(base + 5 * h)] = cmul(X5, w5);
    A[PAD(base + 6 * h)] = cmul(X6, w6);
    A[PAD(base + 7 * h)] = cmul(X7, w7);
}

// Inverse radix-8 DIT stage. If LAST, write real parts only to R.
template <bool LAST>
__device__ __forceinline__ void inv8(float2* __restrict__ A, float* __restrict__ R,
                                     const float2* __restrict__ Tb,
                                     int q, int h, int str) {
    int j    = q & (h - 1);
    int base = ((q - j) << 3) + j;
    float2 w1 = Tb[j * str];
    float2 w2 = cmul(w1, w1);
    float2 w3 = cmul(w2, w1);
    float2 w4 = cmul(w2, w2);
    float2 w5 = cmul(w4, w1);
    float2 w6 = cmul(w4, w2);
    float2 w7 = cmul(w4, w3);
    float2 t0 = A[PAD(base)];
    float2 t1 = cmul(A[PAD(base + h)],     w1);
    float2 t2 = cmul(A[PAD(base + 2 * h)], w2);
    float2 t3 = cmul(A[PAD(base + 3 * h)], w3);
    float2 t4 = cmul(A[PAD(base + 4 * h)], w4);
    float2 t5 = cmul(A[PAD(base + 5 * h)], w5);
    float2 t6 = cmul(A[PAD(base + 6 * h)], w6);
    float2 t7 = cmul(A[PAD(base + 7 * h)], w7);

    float2 a0 = cadd(t0, t4), a1 = cadd(t1, t5), a2 = cadd(t2, t6), a3 = cadd(t3, t7);
    float2 b0 = csub(t0, t4), b1 = csub(t1, t5), b2 = csub(t2, t6), b3 = csub(t3, t7);
    float2 c0 = cadd(a0, a2), c1 = csub(a0, a2), c2 = cadd(a1, a3), c3 = csub(a1, a3);
    float2 X0 = cadd(c0, c2), X4 = csub(c0, c2);
    float2 X2 = make_float2(c1.x - c3.y, c1.y + c3.x);
    float2 X6 = make_float2(c1.x + c3.y, c1.y - c3.x);
    float2 d0 = b0;
    float2 d1 = make_float2(RSQ2 * (b1.x - b1.y), RSQ2 * (b1.y + b1.x));
    float2 d2 = make_float2(-b2.y, b2.x);
    float2 d3 = make_float2(RSQ2 * (-(b3.x + b3.y)), RSQ2 * (b3.x - b3.y));
    float2 e0 = cadd(d0, d2), ee1 = csub(d0, d2), e2 = cadd(d1, d3), e3 = csub(d1, d3);
    float2 X1 = cadd(e0, e2), X5 = csub(e0, e2);
    float2 X3 = make_float2(ee1.x - e3.y, ee1.y + e3.x);
    float2 X7 = make_float2(ee1.x + e3.y, ee1.y - e3.x);

    if (LAST) {
        R[base]         = X0.x;
        R[base + h]     = X1.x;
        R[base + 2 * h] = X2.x;
        R[base + 3 * h] = X3.x;
        R[base + 4 * h] = X4.x;
        R[base + 5 * h] = X5.x;
        R[base + 6 * h] = X6.x;
        R[base + 7 * h] = X7.x;
    } else {
        A[PAD(base)]         = X0;
        A[PAD(base + h)]     = X1;
        A[PAD(base + 2 * h)] = X2;
        A[PAD(base + 3 * h)] = X3;
        A[PAD(base + 4 * h)] = X4;
        A[PAD(base + 5 * h)] = X5;
        A[PAD(base + 6 * h)] = X6;
        A[PAD(base + 7 * h)] = X7;
    }
}

// Fused middle: fwd radix-8 (h=4) in regs + cross-lane radix-4 mid (xor shuffles)
// + inv radix-8 (h=4) in regs. One smem round trip replaces three.
__device__ __forceinline__ void fused_mid(float2* __restrict__ A, const float2* __restrict__ Tb,
                                          int q) {
    const int j = q & 3;
    const int g = q >> 2;
    const int base = 32 * g + j;

    float2 t0 = A[PAD(base)],      t1 = A[PAD(base + 4)];
    float2 t2 = A[PAD(base + 8)],  t3 = A[PAD(base + 12)];
    float2 t4 = A[PAD(base + 16)], t5 = A[PAD(base + 20)];
    float2 t6 = A[PAD(base + 24)], t7 = A[PAD(base + 28)];

    // ---- forward radix-8 DIF (h=4) in registers ----
    float2 a0 = cadd(t0, t4), a1 = cadd(t1, t5), a2 = cadd(t2, t6), a3 = cadd(t3, t7);
    float2 b0 = csub(t0, t4), b1 = csub(t1, t5), b2 = csub(t2, t6), b3 = csub(t3, t7);
    float2 c0 = cadd(a0, a2), c1 = csub(a0, a2), c2 = cadd(a1, a3), c3 = csub(a1, a3);
    float2 X0 = cadd(c0, c2), X4 = csub(c0, c2);
    float2 X2 = make_float2(c1.x + c3.y, c1.y - c3.x);
    float2 X6 = make_float2(c1.x - c3.y, c1.y + c3.x);
    float2 d1 = make_float2(RSQ2 * (b1.x + b1.y), RSQ2 * (b1.y - b1.x));
    float2 d2 = make_float2(b2.y, -b2.x);
    float2 d3 = make_float2(RSQ2 * (b3.y - b3.x), RSQ2 * (-(b3.x + b3.y)));
    float2 e0 = cadd(b0, d2), ee1 = csub(b0, d2), e2 = cadd(d1, d3), e3 = csub(d1, d3);
    float2 X1 = cadd(e0, e2), X5 = csub(e0, e2);
    float2 X3 = make_float2(ee1.x + e3.y, ee1.y - e3.x);
    float2 X7 = make_float2(ee1.x - e3.y, ee1.y + e3.x);

    float2 wc = Tb[j * 64]; wc.y = -wc.y;                  // conj twiddle
    float2 wc2 = cmul(wc, wc), wc3 = cmul(wc2, wc), wc4 = cmul(wc2, wc2);
    float2 y[8];
    y[0] = X0;
    y[1] = cmul(X1, wc);
    y[2] = cmul(X2, wc2);
    y[3] = cmul(X3, wc3);
    y[4] = cmul(X4, wc4);
    y[5] = cmul(X5, cmul(wc4, wc));
    y[6] = cmul(X6, cmul(wc4, wc2));
    y[7] = cmul(X7, cmul(wc4, wc3));

    // ---- cross-lane mid: quad m = 8g + k, lane j = position in quad ----
    const int r_g = ((g & 7) << 3) | (g >> 3);
    float sn, cs;
    __sincosf((float)r_g * 1.5339807878856412e-3f, &sn, &cs);   // 2*pi/4096
    float2 w0b = make_float2(cs * (1.0f / 2048.0f), sn * (1.0f / 2048.0f));
    // lane zeta: F-component held by each lane after S2: lane0=F0(*w0), lane1=F2(*-i w0),
    // lane2=F1(*u w0), lane3=F3(*conj(u) w0)
    float2 zeta = (j == 0) ? make_float2(1.0f, 0.0f)
                : (j == 1) ? make_float2(0.0f, -1.0f)
                : (j == 2) ? make_float2(RSQ2, RSQ2)
                :            make_float2(RSQ2, -RSQ2);
    float2 wbase = cmul(w0b, zeta);
    const bool hi1 = (j & 1) != 0;
    const bool hi2 = (j & 2) != 0;

    #pragma unroll
    for (int k = 0; k < 8; k++) {
        float2 v = y[k];
        float2 s1 = shfl_xor_f2(v, 2);
        float2 u1 = hi2 ? csub(s1, v) : cadd(v, s1);        // lanes0/1: a,c; lanes2/3: bb,d
        float2 s2 = shfl_xor_f2(u1, 1);
        float2 F;
        if (!hi2) F = hi1 ? csub(s2, u1)                                   // F2 = a-c
                          : cadd(u1, s2);                                  // F0 = a+c
        else      F = hi1 ? make_float2(s2.x - u1.y, s2.y + u1.x)          // F3 = bb+i d
                          : make_float2(u1.x + s2.y, u1.y - s2.x);         // F1 = bb-i d
        float2 G = cmul(F, cmul(wbase, Tb[32 * k]));
        float2 s3 = shfl_xor_f2(G, 1);
        float2 z = hi1 ? csub(s3, G) : cadd(G, s3);         // lane0:ap lane1:bp lane2:cp lane3:dp
        float2 s4 = shfl_xor_f2(z, 2);
        float2 out;
        if (!hi2) out = hi1 ? make_float2(z.x - s4.y, z.y + s4.x)          // out1 = bp+i dp
                            : cadd(z, s4);                                  // out0 = ap+cp
        else      out = hi1 ? make_float2(s4.x + z.y, s4.y - z.x)          // out3 = bp-i dp
                            : csub(s4, z);                                  // out2 = ap-cp
        y[k] = out;
    }

    // ---- inverse radix-8 DIT (h=4) in registers ----
    float2 v1 = Tb[j * 64];
    float2 v2 = cmul(v1, v1), v3 = cmul(v2, v1), v4 = cmul(v2, v2);
    float2 u0 = y[0];
    float2 u1b = cmul(y[1], v1);
    float2 u2 = cmul(y[2], v2);
    float2 u3 = cmul(y[3], v3);
    float2 u4 = cmul(y[4], v4);
    float2 u5 = cmul(y[5], cmul(v4, v1));
    float2 u6 = cmul(y[6], cmul(v4, v2));
    float2 u7 = cmul(y[7], cmul(v4, v3));

    float2 A0 = cadd(u0, u4), A1 = cadd(u1b, u5), A2 = cadd(u2, u6), A3 = cadd(u3, u7);
    float2 B0 = csub(u0, u4), B1 = csub(u1b, u5), B2 = csub(u2, u6), B3 = csub(u3, u7);
    float2 C0 = cadd(A0, A2), C1 = csub(A0, A2), C2 = cadd(A1, A3), C3 = csub(A1, A3);
    float2 Z0 = cadd(C0, C2), Z4 = csub(C0, C2);
    float2 Z2 = make_float2(C1.x - C3.y, C1.y + C3.x);
    float2 Z6 = make_float2(C1.x + C3.y, C1.y - C3.x);
    float2 D1 = make_float2(RSQ2 * (B1.x - B1.y), RSQ2 * (B1.y + B1.x));
    float2 D2 = make_float2(-B2.y, B2.x);
    float2 D3 = make_float2(RSQ2 * (-(B3.x + B3.y)), RSQ2 * (B3.x - B3.y));
    float2 E0 = cadd(B0, D2), E1 = csub(B0, D2), E2 = cadd(D1, D3), E3 = csub(D1, D3);
    float2 Z1 = cadd(E0, E2), Z5 = csub(E0, E2);
    float2 Z3 = make_float2(E1.x - E3.y, E1.y + E3.x);
    float2 Z7 = make_float2(E1.x + E3.y, E1.y - E3.x);

    A[PAD(base)]      = Z0;
    A[PAD(base + 4)]  = Z1;
    A[PAD(base + 8)]  = Z2;
    A[PAD(base + 12)] = Z3;
    A[PAD(base + 16)] = Z4;
    A[PAD(base + 20)] = Z5;
    A[PAD(base + 24)] = Z6;
    A[PAD(base + 28)] = Z7;
}

// store nt consecutive t-slices of batch b's output (both quads owned by tid)
__device__ __forceinline__ void store_slice(const float* __restrict__ pr,
                                            const float* __restrict__ R0,
                                            const float* __restrict__ R1,
                                            float4* __restrict__ out,
                                            long long n0, long long cap_f4,
                                            int b, int tid, int t0, int nt) {
    const long long base = (long long)b * 4096;
    const long long obf4 = (long long)b * (NT * NSC / 4);
    const bool ok = (obf4 + (long long)NT * (NSC / 4) <= cap_f4) && (base + 4096 <= n0);
    const float2* pr2 = (const float2*)pr;
    const float2* R0v = (const float2*)R0;
    const float2* R1v = (const float2*)R1;
    #pragma unroll
    for (int wq = 0; wq < 2; wq++) {
        int u = tid + wq * THREADS;
        float2 e0, e1;
        if (ok) {
            e0 = pr2[(base >> 1) + u];
            e1 = pr2[(base >> 1) + 1024 + u];
        } else {
            e0.x = (base + 2 * u < n0) ? pr[base + 2 * u] : 0.0f;
            e0.y = (base + 2 * u + 1 < n0) ? pr[base + 2 * u + 1] : 0.0f;
            e1.x = (base + 2048 + 2 * u < n0) ? pr[base + 2048 + 2 * u] : 0.0f;
            e1.y = (base + 2048 + 2 * u + 1 < n0) ? pr[base + 2048 + 2 * u + 1] : 0.0f;
        }
        float2 o0 = R0v[u];
        float2 o1 = R1v[u];
        for (int dt = 0; dt < nt; dt++) {
            int t = t0 + dt;
            float w = c_w[t];
            float4 v;
            v.x = e0.x + (e1.x - e0.x) * w;
            v.y = o0.x + (o1.x - o0.x) * w;
            v.z = e0.y + (e1.y - e0.y) * w;
            v.w = o0.y + (o1.y - o0.y) * w;
            long long f4 = obf4 + (long long)t * (NSC / 4) + u;
            if (ok)               out[f4] = v;
            else if (f4 < cap_f4) out[f4] = v;
        }
    }
}

__device__ __forceinline__ void load_half(const float* __restrict__ pr,
                                          const float* __restrict__ pi,
                                          float2* __restrict__ Yq,
                                          long long n0, long long n1,
                                          int b, int q, int sel) {
    const long long base = (long long)b * 4096 + (long long)sel * 2048;
    #pragma unroll
    for (int i = 0; i < 8; i++) {
        int n = q + i * 256;
        long long idx = base + n;
        float r = (idx < n0) ? pr[idx] : 0.0f;
        float m = (idx < n1) ? pi[idx] : 0.0f;
        Yq[PAD(n)] = make_float2(r, m);
    }
}

__global__ __launch_bounds__(THREADS, 2) void tdi_kernel(const float* __restrict__ pr,
                                                         const float* __restrict__ pi,
                                                         float4* __restrict__ out,
                                                         long long n0, long long n1,
                                                         long long cap_f4, int B)
{
    extern __shared__ float2 sh[];
    float2* Tb = sh;                    // 256 entries
    float2* Y0 = sh + 256;
    float2* Y1 = sh + 2560;
    float*  R0 = (float*)(sh + 4864);
    float*  R1 = R0 + 2048;

    const int tid = threadIdx.x;
    const int q   = tid & 255;
    const int sel = tid >> 8;
    const int bA  = 2 * blockIdx.x;
    int bB        = 2 * blockIdx.x + 1;
    if (bB >= B) bB = bA;

    if (tid < 256) {
        float s, c;
        __sincosf((float)tid * 3.0679615757712823e-3f, &s, &c);   // 2*pi/2048
        Tb[tid] = make_float2(c, s);
    }
    float2* Yq = sel ? Y1 : Y0;
    float*  Rq = sel ? R1 : R0;
    load_half(pr, pi, Yq, n0, n1, bA, q, sel);
    __syncthreads();

    // ---- FFT batch A ----
    fwd8(Yq, Tb, q, 256, 1);  hsync(sel);
    fwd8(Yq, Tb, q, 32,  8);  hsync(sel);
    fused_mid(Yq, Tb, q);     hsync(sel);
    inv8<false>(Yq, (float*)0, Tb, q, 32, 8);  hsync(sel);
    inv8<true> (Yq, Rq, Tb, q, 256, 1);
    __syncthreads();

    // ---- load batch B ----
    load_half(pr, pi, Yq, n0, n1, bB, q, sel);
    hsync(sel);

    // ---- FFT batch B with batch-A stores in the stage gaps ----
    store_slice(pr, R0, R1, out, n0, cap_f4, bA, tid, 0, 3);
    fwd8(Yq, Tb, q, 256, 1);  hsync(sel);
    store_slice(pr, R0, R1, out, n0, cap_f4, bA, tid, 3, 3);
    fwd8(Yq, Tb, q, 32,  8);  hsync(sel);
    store_slice(pr, R0, R1, out, n0, cap_f4, bA, tid, 6, 3);
    fused_mid(Yq, Tb, q);     hsync(sel);
    store_slice(pr, R0, R1, out, n0, cap_f4, bA, tid, 9, 3);
    inv8<false>(Yq, (float*)0, Tb, q, 32, 8);  hsync(sel);
    store_slice(pr, R0, R1, out, n0, cap_f4, bA, tid, 12, 2);
    __syncthreads();                    // all A-stores done before R overwritten
    inv8<true> (Yq, Rq, Tb, q, 256, 1);
    __syncthreads();

    // ---- tail: store batch B ----
    store_slice(pr, R0, R1, out, n0, cap_f4, bB, tid, 0, NT);
}

extern "C" void kernel_launch(void* const* d_in, const int* in_sizes, int n_in,
                              void* d_out, int out_size) {
    const float* pr = (const float*)d_in[0];
    const int ilast = (n_in > 1) ? (n_in - 1) : 0;
    const float* pi = (const float*)d_in[ilast];

    const long long n0 = (long long)in_sizes[0];
    const long long n1 = (long long)in_sizes[ilast];

    long long B = n0 / 4096;
    long long B_cap = (long long)out_size / ((long long)NT * NSC);
    if (B_cap < B) B = B_cap;
    if (B < 1) B = 1;
    if (B > 65535) B = 65535;

    const long long cap_f4 = (long long)out_size / 4;
    const int grid = (int)((B + 1) / 2);

    static bool attr_done = false;
    if (!attr_done) {
        cudaFuncSetAttribute(tdi_kernel, cudaFuncAttributeMaxDynamicSharedMemorySize, SMEM_BYTES);
        attr_done = true;
    }
    tdi_kernel<<<grid, THREADS, SMEM_BYTES>>>(pr, pi, (float4*)d_out, n0, n1, cap_f4, (int)B);
}